// round 1
// baseline (speedup 1.0000x reference)
#include <cuda_runtime.h>
#include <cuda_bf16.h>
#include <math.h>

// Problem constants
#define NROWS 4096
#define TWO_N 8192
#define D 128
#define INV_T 10.0f      // 1/temperature
#define CSHIFT 10.0f     // max possible logit (cos sim <= 1)

// GEMM tiling
#define BM 64
#define BN 64
#define SROW 132         // padded smem row stride (floats): 128 + 4, keeps 16B align, kills bank conflicts

// Scratch (static device globals: allocation-free)
__device__ float g_rn[TWO_N * D];   // normalized reps, row-major
__device__ float g_pos[TWO_N];      // positive-pair cosine sims

// ---------------------------------------------------------------------------
// packed fp32x2 FMA (FFMA2) helpers — PTX-only path, doubles fp32 throughput
// ---------------------------------------------------------------------------
__device__ __forceinline__ void ffma2(unsigned long long& acc,
                                      float ax, float ay,
                                      float bx, float by) {
    unsigned long long av, bv;
    asm("mov.b64 %0, {%1, %2};" : "=l"(av) : "f"(ax), "f"(ay));
    asm("mov.b64 %0, {%1, %2};" : "=l"(bv) : "f"(bx), "f"(by));
    asm("fma.rn.f32x2 %0, %1, %2, %0;" : "+l"(acc) : "l"(av), "l"(bv));
}

__device__ __forceinline__ float unpack_sum(unsigned long long v) {
    float lo, hi;
    asm("mov.b64 {%0, %1}, %2;" : "=f"(lo), "=f"(hi) : "l"(v));
    return lo + hi;
}

// ---------------------------------------------------------------------------
// Kernel 1: row-normalize reps = concat(z_i, z_j). One warp per row.
// ---------------------------------------------------------------------------
__global__ void k_norm(const float* __restrict__ zi, const float* __restrict__ zj) {
    int warp = threadIdx.x >> 5;
    int lane = threadIdx.x & 31;
    int r = blockIdx.x * 8 + warp;
    const float* src = (r < NROWS) ? (zi + (size_t)r * D)
                                   : (zj + (size_t)(r - NROWS) * D);
    float4 v = ((const float4*)src)[lane];
    float ss = v.x * v.x + v.y * v.y + v.z * v.z + v.w * v.w;
    #pragma unroll
    for (int o = 16; o; o >>= 1) ss += __shfl_xor_sync(0xffffffffu, ss, o);
    float inv = 1.0f / fmaxf(sqrtf(ss), 1e-8f);
    float4 w;
    w.x = v.x * inv; w.y = v.y * inv; w.z = v.z * inv; w.w = v.w * inv;
    ((float4*)(g_rn + (size_t)r * D))[lane] = w;
}

// ---------------------------------------------------------------------------
// Kernel 2: positive pair sims pos[r] = dot(rn[r], rn[(r+N) mod 2N]).
// Also zeroes d_out (poisoned by harness).
// ---------------------------------------------------------------------------
__global__ void k_pos(float* __restrict__ d_out) {
    int warp = threadIdx.x >> 5;
    int lane = threadIdx.x & 31;
    int r = blockIdx.x * 8 + warp;
    int p = (r + NROWS) & (TWO_N - 1);
    float4 a = ((const float4*)(g_rn + (size_t)r * D))[lane];
    float4 b = ((const float4*)(g_rn + (size_t)p * D))[lane];
    float s = a.x * b.x + a.y * b.y + a.z * b.z + a.w * b.w;
    #pragma unroll
    for (int o = 16; o; o >>= 1) s += __shfl_xor_sync(0xffffffffu, s, o);
    if (lane == 0) g_pos[r] = s;
    if (blockIdx.x == 0 && threadIdx.x == 0) d_out[0] = 0.0f;
}

// ---------------------------------------------------------------------------
// Kernel 3: fused sim-GEMM + exp-rowsum + loss.
// Block = 256 threads handles BM=64 rows of i; loops over all j in BN=64 tiles.
// Micro-tile 4x4 per thread, strided: i = ty + 16*ii, j = tx + 16*jj.
// f32x2 lanes pair even/odd k.
// ---------------------------------------------------------------------------
__global__ __launch_bounds__(256)
void k_main(float* __restrict__ d_out) {
    extern __shared__ float sm[];
    float* As = sm;                 // [BM][SROW]
    float* Bs = sm + BM * SROW;     // [BN][SROW]

    __shared__ float bsum;

    const int t  = threadIdx.x;
    const int tx = t & 15;
    const int ty = t >> 4;
    const int iBase = blockIdx.x * BM;

    if (t == 0) bsum = 0.0f;

    // Load A tile (64 rows x 128 k) once: coalesced float4 loads, natural layout.
    #pragma unroll
    for (int rep = 0; rep < 8; rep++) {
        int linear = rep * 256 + t;
        int row = linear >> 5;       // 0..63
        int kq  = linear & 31;       // float4 index within row
        float4 v = *(const float4*)(g_rn + (size_t)(iBase + row) * D + kq * 4);
        *(float4*)(As + row * SROW + kq * 4) = v;
    }

    float rsum[4] = {0.f, 0.f, 0.f, 0.f};

    for (int jBase = 0; jBase < TWO_N; jBase += BN) {
        __syncthreads();   // protect Bs from readers of previous tile (and covers A on iter 0)
        #pragma unroll
        for (int rep = 0; rep < 8; rep++) {
            int linear = rep * 256 + t;
            int row = linear >> 5;
            int kq  = linear & 31;
            float4 v = *(const float4*)(g_rn + (size_t)(jBase + row) * D + kq * 4);
            *(float4*)(Bs + row * SROW + kq * 4) = v;
        }
        __syncthreads();

        unsigned long long acc[4][4];
        #pragma unroll
        for (int a = 0; a < 4; a++)
            #pragma unroll
            for (int b = 0; b < 4; b++) acc[a][b] = 0ull;  // bit pattern == (0.f, 0.f)

        #pragma unroll 2
        for (int k = 0; k < D; k += 4) {
            float4 a4[4], b4[4];
            #pragma unroll
            for (int ii = 0; ii < 4; ii++)
                a4[ii] = *(const float4*)(As + (ty + 16 * ii) * SROW + k);
            #pragma unroll
            for (int jj = 0; jj < 4; jj++)
                b4[jj] = *(const float4*)(Bs + (tx + 16 * jj) * SROW + k);
            #pragma unroll
            for (int ii = 0; ii < 4; ii++) {
                #pragma unroll
                for (int jj = 0; jj < 4; jj++) {
                    ffma2(acc[ii][jj], a4[ii].x, a4[ii].y, b4[jj].x, b4[jj].y);
                    ffma2(acc[ii][jj], a4[ii].z, a4[ii].w, b4[jj].z, b4[jj].w);
                }
            }
        }

        // exp and accumulate into per-thread row sums
        #pragma unroll
        for (int ii = 0; ii < 4; ii++) {
            float rs = 0.0f;
            #pragma unroll
            for (int jj = 0; jj < 4; jj++) {
                float s = unpack_sum(acc[ii][jj]);
                rs += __expf(fmaf(INV_T, s, -CSHIFT));
            }
            rsum[ii] += rs;
        }
    }

    // Reduce row sums across the 16 tx lanes (lane = (ty&1)*16 + tx, xor on low 4 bits)
    float lsum = 0.0f;
    #pragma unroll
    for (int ii = 0; ii < 4; ii++) {
        float v = rsum[ii];
        v += __shfl_xor_sync(0xffffffffu, v, 1);
        v += __shfl_xor_sync(0xffffffffu, v, 2);
        v += __shfl_xor_sync(0xffffffffu, v, 4);
        v += __shfl_xor_sync(0xffffffffu, v, 8);
        if (tx == 0) {
            int i = iBase + ty + 16 * ii;
            float p = g_pos[i];
            float S = v + __expf(fmaf(INV_T, p, -CSHIFT));   // prepended positives column
            lsum += logf(S) + CSHIFT - INV_T * p;            // LSE - pos/T
        }
    }
    if (tx == 0) atomicAdd(&bsum, lsum);
    __syncthreads();
    if (t == 0) atomicAdd(d_out, bsum * (1.0f / (float)TWO_N));
}

// ---------------------------------------------------------------------------
extern "C" void kernel_launch(void* const* d_in, const int* in_sizes, int n_in,
                              void* d_out, int out_size) {
    const float* zi = (const float*)d_in[0];
    const float* zj = (const float*)d_in[1];
    float* out = (float*)d_out;

    static int smem_set = 0;
    (void)smem_set;
    size_t smem = (size_t)(BM + BN) * SROW * sizeof(float);  // 67584 B
    cudaFuncSetAttribute(k_main, cudaFuncAttributeMaxDynamicSharedMemorySize, (int)smem);

    k_norm<<<TWO_N / 8, 256>>>(zi, zj);
    k_pos<<<TWO_N / 8, 256>>>(out);
    k_main<<<TWO_N / BM, 256, smem>>>(out);
}

// round 3
// speedup vs baseline: 3.9301x; 3.9301x over previous
#include <cuda_runtime.h>
#include <cuda_bf16.h>
#include <math.h>
#include <stdint.h>

#define NROWS 4096
#define TWO_N 8192
#define D 128
#define NT 32                       // j-tiles of 128 per CTA
#define K2C 14.4269504088896340f    // 10 / ln(2)

// ---------------- device scratch (allocation-free) ----------------
__device__ float          g_rn[TWO_N * D];
__device__ __nv_bfloat16  g_hi[TWO_N * D];
__device__ __nv_bfloat16  g_lo[TWO_N * D];
__device__ float          g_pos[TWO_N];
__device__ float          g_rowsum[2 * TWO_N];

// ---------------- smem map (dynamic) ----------------
#define SM_A_HI   0
#define SM_A_LO   32768
#define SM_B(s)   (65536 + (s) * 65536)     // hi @ +0, lo @ +32768
#define SM_RED    196608
#define SMEM_BYTES (196608 + 128 * 4 * 4)   // + reduction buffer

// ---------------- helpers ----------------
__device__ __forceinline__ uint32_t smem_u32(const void* p) {
    uint32_t a;
    asm("{ .reg .u64 t; cvta.to.shared.u64 t, %1; cvt.u32.u64 %0, t; }" : "=r"(a) : "l"(p));
    return a;
}
__device__ __forceinline__ float ex2f(float x) {
    float r; asm("ex2.approx.ftz.f32 %0, %1;" : "=f"(r) : "f"(x)); return r;
}
__device__ __forceinline__ void ldsm4(uint32_t* r, uint32_t addr) {
    asm volatile("ldmatrix.sync.aligned.m8n8.x4.shared.b16 {%0,%1,%2,%3}, [%4];"
                 : "=r"(r[0]), "=r"(r[1]), "=r"(r[2]), "=r"(r[3]) : "r"(addr));
}
__device__ __forceinline__ void mma_bf16(float* d, const uint32_t* a, uint32_t b0, uint32_t b1) {
    asm volatile("mma.sync.aligned.m16n8k16.row.col.f32.bf16.bf16.f32 "
                 "{%0,%1,%2,%3}, {%4,%5,%6,%7}, {%8,%9}, {%0,%1,%2,%3};"
                 : "+f"(d[0]), "+f"(d[1]), "+f"(d[2]), "+f"(d[3])
                 : "r"(a[0]), "r"(a[1]), "r"(a[2]), "r"(a[3]), "r"(b0), "r"(b1));
}
#define CP_ASYNC16(sa, ga) \
    asm volatile("cp.async.cg.shared.global [%0], [%1], 16;" :: "r"(sa), "l"(ga))
#define CP_COMMIT() asm volatile("cp.async.commit_group;" ::: "memory")
#define CP_WAIT1()  asm volatile("cp.async.wait_group 1;" ::: "memory")

// ---------------------------------------------------------------------------
// Kernel 1: normalize rows + bf16 hi/lo split. One warp per row.
// ---------------------------------------------------------------------------
__global__ void k_norm(const float* __restrict__ zi, const float* __restrict__ zj) {
    int warp = threadIdx.x >> 5, lane = threadIdx.x & 31;
    int r = blockIdx.x * 8 + warp;
    const float* src = (r < NROWS) ? (zi + (size_t)r * D) : (zj + (size_t)(r - NROWS) * D);
    float4 v = ((const float4*)src)[lane];
    float ss = v.x * v.x + v.y * v.y + v.z * v.z + v.w * v.w;
    #pragma unroll
    for (int o = 16; o; o >>= 1) ss += __shfl_xor_sync(0xffffffffu, ss, o);
    float inv = 1.0f / fmaxf(sqrtf(ss), 1e-8f);
    float4 w; w.x = v.x*inv; w.y = v.y*inv; w.z = v.z*inv; w.w = v.w*inv;
    ((float4*)(g_rn + (size_t)r * D))[lane] = w;

    __nv_bfloat16 h[4], l[4];
    float wf[4] = {w.x, w.y, w.z, w.w};
    #pragma unroll
    for (int q = 0; q < 4; q++) {
        h[q] = __float2bfloat16(wf[q]);
        l[q] = __float2bfloat16(wf[q] - __bfloat162float(h[q]));
    }
    *(uint2*)(g_hi + (size_t)r * D + lane * 4) = *(uint2*)h;
    *(uint2*)(g_lo + (size_t)r * D + lane * 4) = *(uint2*)l;
}

// ---------------------------------------------------------------------------
// Kernel 2: positive-pair sims. One warp per row.
// ---------------------------------------------------------------------------
__global__ void k_pos() {
    int warp = threadIdx.x >> 5, lane = threadIdx.x & 31;
    int r = blockIdx.x * 8 + warp;
    int p = (r + NROWS) & (TWO_N - 1);
    float4 a = ((const float4*)(g_rn + (size_t)r * D))[lane];
    float4 b = ((const float4*)(g_rn + (size_t)p * D))[lane];
    float s = a.x*b.x + a.y*b.y + a.z*b.z + a.w*b.w;
    #pragma unroll
    for (int o = 16; o; o >>= 1) s += __shfl_xor_sync(0xffffffffu, s, o);
    if (lane == 0) g_pos[r] = s;
}

// ---------------------------------------------------------------------------
// B-tile async loader: 128 rows x 128 bf16 (hi & lo), XOR-swizzled 16B chunks
// ---------------------------------------------------------------------------
__device__ __forceinline__ void load_B(uint32_t sb, uint32_t off, int rowBase, int t) {
    #pragma unroll
    for (int rep = 0; rep < 8; rep++) {
        int idx = rep * 256 + t;          // 0..2047
        int row = idx >> 4, ch = idx & 15;
        uint32_t so = off + (uint32_t)(row * 256) + ((uint32_t)(ch ^ (row & 7)) << 4);
        const void* gh = g_hi + (size_t)(rowBase + row) * D + ch * 8;
        const void* gl = g_lo + (size_t)(rowBase + row) * D + ch * 8;
        CP_ASYNC16(sb + so, gh);
        CP_ASYNC16(sb + so + 32768u, gl);
    }
}

// ---------------------------------------------------------------------------
// Kernel 3: fused sim-GEMM (mma.sync bf16, 3-product fp32 emulation) + exp sums
// grid = 128: iTile = blockIdx>>1, jHalf = blockIdx&1. 256 threads = 8 warps.
// ---------------------------------------------------------------------------
__global__ __launch_bounds__(256, 1)
void k_main() {
    extern __shared__ char sm[];
    const uint32_t sb = smem_u32(sm);
    const int t = threadIdx.x, lane = t & 31, wid = t >> 5;
    const int warpM = wid >> 2, warpN = wid & 3;
    const int iBase  = (blockIdx.x >> 1) * 128;
    const int jBase0 = (blockIdx.x & 1) * 4096;

    // A tile (hi+lo), plain loads, swizzled
    #pragma unroll
    for (int rep = 0; rep < 8; rep++) {
        int idx = rep * 256 + t;
        int row = idx >> 4, ch = idx & 15;
        uint32_t so = (uint32_t)(row * 256) + ((uint32_t)(ch ^ (row & 7)) << 4);
        *(uint4*)(sm + SM_A_HI + so) = *(const uint4*)(g_hi + (size_t)(iBase + row) * D + ch * 8);
        *(uint4*)(sm + SM_A_LO + so) = *(const uint4*)(g_lo + (size_t)(iBase + row) * D + ch * 8);
    }

    // prologue: B stages 0,1
    load_B(sb, SM_B(0), jBase0,       t); CP_COMMIT();
    load_B(sb, SM_B(1), jBase0 + 128, t); CP_COMMIT();

    // lane-constant ldmatrix address pieces
    const int r7   = lane & 7;
    const int rowA = (lane & 7) + ((lane >> 3) & 1) * 8;  const int c4A = lane >> 4;
    const int rowB = (lane & 7) + ((lane >> 4) << 3);     const int c4B = (lane >> 3) & 1;

    uint32_t aRowHi[4], aRowLo[4];
    #pragma unroll
    for (int mt = 0; mt < 4; mt++) {
        uint32_t ro = (uint32_t)((warpM * 64 + mt * 16 + rowA) * 256);
        aRowHi[mt] = sb + SM_A_HI + ro;
        aRowLo[mt] = sb + SM_A_LO + ro;
    }
    uint32_t bRow[2];
    #pragma unroll
    for (int g = 0; g < 2; g++)
        bRow[g] = (uint32_t)((warpN * 32 + g * 16 + rowB) * 256);

    float rsum[8];
    #pragma unroll
    for (int u = 0; u < 8; u++) rsum[u] = 0.0f;

    for (int tt = 0; tt < NT; tt++) {
        CP_WAIT1();
        __syncthreads();
        const uint32_t bHiBase = sb + SM_B(tt & 1);
        const uint32_t bLoBase = bHiBase + 32768u;

        float d[4][4][4];
        #pragma unroll
        for (int mt = 0; mt < 4; mt++)
            #pragma unroll
            for (int nt = 0; nt < 4; nt++)
                #pragma unroll
                for (int q = 0; q < 4; q++) d[mt][nt][q] = 0.0f;

        #pragma unroll
        for (int ks = 0; ks < 8; ks++) {
            uint32_t ah[4][4], al[4][4], bh[8], bl[8];
            const uint32_t offA = (uint32_t)(((2 * ks + c4A) ^ r7) << 4);
            const uint32_t offB = (uint32_t)(((2 * ks + c4B) ^ r7) << 4);
            #pragma unroll
            for (int mt = 0; mt < 4; mt++) {
                ldsm4(ah[mt], aRowHi[mt] + offA);
                ldsm4(al[mt], aRowLo[mt] + offA);
            }
            #pragma unroll
            for (int g = 0; g < 2; g++) {
                ldsm4(bh + g * 4, bHiBase + bRow[g] + offB);
                ldsm4(bl + g * 4, bLoBase + bRow[g] + offB);
            }
            #pragma unroll
            for (int mt = 0; mt < 4; mt++) {
                #pragma unroll
                for (int nt = 0; nt < 4; nt++) {
                    mma_bf16(d[mt][nt], ah[mt], bh[nt * 2], bh[nt * 2 + 1]);
                    mma_bf16(d[mt][nt], ah[mt], bl[nt * 2], bl[nt * 2 + 1]);
                    mma_bf16(d[mt][nt], al[mt], bh[nt * 2], bh[nt * 2 + 1]);
                }
            }
        }
        __syncthreads();   // all reads of buf[tt&1] done before refill
        if (tt + 2 < NT) { load_B(sb, SM_B(tt & 1), jBase0 + (tt + 2) * 128, t); CP_COMMIT(); }

        // epilogue: exp and accumulate per-row partials
        #pragma unroll
        for (int mt = 0; mt < 4; mt++) {
            float s0 = 0.0f, s1 = 0.0f;
            #pragma unroll
            for (int nt = 0; nt < 4; nt++) {
                s0 += ex2f(fmaf(d[mt][nt][0], K2C, -K2C));
                s0 += ex2f(fmaf(d[mt][nt][1], K2C, -K2C));
                s1 += ex2f(fmaf(d[mt][nt][2], K2C, -K2C));
                s1 += ex2f(fmaf(d[mt][nt][3], K2C, -K2C));
            }
            rsum[mt * 2 + 0] += s0;
            rsum[mt * 2 + 1] += s1;
        }
    }

    // cross-warp row reduction
    __syncthreads();
    float* red = (float*)(sm + SM_RED);   // [128][4]
    #pragma unroll
    for (int u = 0; u < 8; u++) {
        int mt = u >> 1, h = u & 1;
        float v = rsum[u];
        v += __shfl_xor_sync(0xffffffffu, v, 1);
        v += __shfl_xor_sync(0xffffffffu, v, 2);
        if ((lane & 3) == 0) {
            int r = warpM * 64 + mt * 16 + h * 8 + (lane >> 2);
            red[r * 4 + warpN] = v;
        }
    }
    __syncthreads();
    if (t < 128) {
        float s = red[t * 4] + red[t * 4 + 1] + red[t * 4 + 2] + red[t * 4 + 3];
        g_rowsum[(blockIdx.x & 1) * TWO_N + iBase + t] = s;
    }
}

// ---------------------------------------------------------------------------
// Kernel 4: final loss (single block, deterministic)
// ---------------------------------------------------------------------------
__global__ void k_final(float* __restrict__ out) {
    __shared__ float red[1024];
    float acc = 0.0f;
    for (int r = threadIdx.x; r < TWO_N; r += 1024) {
        float S = g_rowsum[r] + g_rowsum[TWO_N + r];
        float p = g_pos[r];
        float Sf = S + expf(fmaf(10.0f, p, -10.0f));
        acc += logf(Sf) + 10.0f - 10.0f * p;
    }
    red[threadIdx.x] = acc;
    __syncthreads();
    for (int s = 512; s; s >>= 1) {
        if (threadIdx.x < s) red[threadIdx.x] += red[threadIdx.x + s];
        __syncthreads();
    }
    if (threadIdx.x == 0) out[0] = red[0] * (1.0f / (float)TWO_N);
}

// ---------------------------------------------------------------------------
extern "C" void kernel_launch(void* const* d_in, const int* in_sizes, int n_in,
                              void* d_out, int out_size) {
    const float* zi = (const float*)d_in[0];
    const float* zj = (const float*)d_in[1];
    float* out = (float*)d_out;

    cudaFuncSetAttribute(k_main, cudaFuncAttributeMaxDynamicSharedMemorySize, SMEM_BYTES);

    k_norm<<<TWO_N / 8, 256>>>(zi, zj);
    k_pos<<<TWO_N / 8, 256>>>();
    k_main<<<128, 256, SMEM_BYTES>>>();
    k_final<<<1, 1024>>>(out);
}

// round 4
// speedup vs baseline: 6.1742x; 1.5710x over previous
#include <cuda_runtime.h>
#include <cuda_bf16.h>
#include <math.h>
#include <stdint.h>

#define NROWS 4096
#define TWO_N 8192
#define D 128
#define NTILE 64                    // 8192 / 128
#define NJOBS 2080                  // 64*65/2 triangle tiles
#define JOBS_PER_CTA 16
#define GRID_MAIN 130               // 130*16 = 2080
#define K2C 14.4269504088896340f    // 10 / ln(2)

// ---------------- device scratch (allocation-free) ----------------
__device__ __nv_bfloat16  g_hi[TWO_N * D];
__device__ __nv_bfloat16  g_lo[TWO_N * D];
__device__ float          g_pos[TWO_N];
__device__ float          g_part[NTILE * NTILE * 128];   // [I][J][row] partial exp-sums
__device__ float          g_loss[TWO_N];

// ---------------- smem map (dynamic) ----------------
#define SM_A_HI   0
#define SM_A_LO   32768
#define SM_B(s)   (65536 + (s) * 65536)     // hi @ +0, lo @ +32768
#define SM_ROWRED 196608                    // [128][4] floats = 2KB
#define SM_COLRED 198656                    // [128][2] floats = 1KB
#define SMEM_BYTES 199680

// ---------------- helpers ----------------
__device__ __forceinline__ uint32_t smem_u32(const void* p) {
    uint32_t a;
    asm("{ .reg .u64 t; cvta.to.shared.u64 t, %1; cvt.u32.u64 %0, t; }" : "=r"(a) : "l"(p));
    return a;
}
__device__ __forceinline__ float ex2f(float x) {
    float r; asm("ex2.approx.ftz.f32 %0, %1;" : "=f"(r) : "f"(x)); return r;
}
__device__ __forceinline__ void ldsm4(uint32_t* r, uint32_t addr) {
    asm volatile("ldmatrix.sync.aligned.m8n8.x4.shared.b16 {%0,%1,%2,%3}, [%4];"
                 : "=r"(r[0]), "=r"(r[1]), "=r"(r[2]), "=r"(r[3]) : "r"(addr));
}
__device__ __forceinline__ void mma_bf16(float* d, const uint32_t* a, uint32_t b0, uint32_t b1) {
    asm volatile("mma.sync.aligned.m16n8k16.row.col.f32.bf16.bf16.f32 "
                 "{%0,%1,%2,%3}, {%4,%5,%6,%7}, {%8,%9}, {%0,%1,%2,%3};"
                 : "+f"(d[0]), "+f"(d[1]), "+f"(d[2]), "+f"(d[3])
                 : "r"(a[0]), "r"(a[1]), "r"(a[2]), "r"(a[3]), "r"(b0), "r"(b1));
}
#define CP_ASYNC16(sa, ga) \
    asm volatile("cp.async.cg.shared.global [%0], [%1], 16;" :: "r"(sa), "l"(ga))
#define CP_COMMIT() asm volatile("cp.async.commit_group;" ::: "memory")
#define CP_WAIT1()  asm volatile("cp.async.wait_group 1;" ::: "memory")

// triangle job -> (I,J), J >= I
__device__ __forceinline__ void job_ij(int g, int& I, int& J) {
    int i = 0, off = 0;
    while (off + (NTILE - i) <= g) { off += NTILE - i; i++; }
    I = i; J = i + (g - off);
}
__device__ __forceinline__ void job_adv(int& I, int& J) {
    if (++J == NTILE) { ++I; J = I; }
}

// ---------------------------------------------------------------------------
// Kernel 1: normalize pair rows (r, r+N), bf16 hi/lo split, positive sims.
// One warp per pair. Never materializes fp32 normalized reps.
// ---------------------------------------------------------------------------
__global__ void k_prep(const float* __restrict__ zi, const float* __restrict__ zj) {
    int warp = threadIdx.x >> 5, lane = threadIdx.x & 31;
    int p = blockIdx.x * 8 + warp;                // pair index 0..4095
    float4 a = ((const float4*)(zi + (size_t)p * D))[lane];
    float4 b = ((const float4*)(zj + (size_t)p * D))[lane];
    float sa = a.x*a.x + a.y*a.y + a.z*a.z + a.w*a.w;
    float sb = b.x*b.x + b.y*b.y + b.z*b.z + b.w*b.w;
    float dp = a.x*b.x + a.y*b.y + a.z*b.z + a.w*b.w;
    #pragma unroll
    for (int o = 16; o; o >>= 1) {
        sa += __shfl_xor_sync(0xffffffffu, sa, o);
        sb += __shfl_xor_sync(0xffffffffu, sb, o);
        dp += __shfl_xor_sync(0xffffffffu, dp, o);
    }
    float ia = 1.0f / fmaxf(sqrtf(sa), 1e-8f);
    float ib = 1.0f / fmaxf(sqrtf(sb), 1e-8f);
    if (lane == 0) {
        float pos = dp * ia * ib;
        g_pos[p] = pos;
        g_pos[p + NROWS] = pos;
    }
    float wa[4] = {a.x*ia, a.y*ia, a.z*ia, a.w*ia};
    float wb[4] = {b.x*ib, b.y*ib, b.z*ib, b.w*ib};
    __nv_bfloat16 ha[4], la[4], hb[4], lb[4];
    #pragma unroll
    for (int q = 0; q < 4; q++) {
        ha[q] = __float2bfloat16(wa[q]); la[q] = __float2bfloat16(wa[q] - __bfloat162float(ha[q]));
        hb[q] = __float2bfloat16(wb[q]); lb[q] = __float2bfloat16(wb[q] - __bfloat162float(hb[q]));
    }
    *(uint2*)(g_hi + (size_t)p * D + lane * 4) = *(uint2*)ha;
    *(uint2*)(g_lo + (size_t)p * D + lane * 4) = *(uint2*)la;
    *(uint2*)(g_hi + (size_t)(p + NROWS) * D + lane * 4) = *(uint2*)hb;
    *(uint2*)(g_lo + (size_t)(p + NROWS) * D + lane * 4) = *(uint2*)lb;
}

// ---------------------------------------------------------------------------
// tile loaders (XOR-swizzled 16B chunks, 256B rows)
// ---------------------------------------------------------------------------
__device__ __forceinline__ void load_B_async(uint32_t sb, uint32_t off, int rowBase, int t) {
    #pragma unroll
    for (int rep = 0; rep < 8; rep++) {
        int idx = rep * 256 + t;
        int row = idx >> 4, ch = idx & 15;
        uint32_t so = off + (uint32_t)(row * 256) + ((uint32_t)(ch ^ (row & 7)) << 4);
        CP_ASYNC16(sb + so,          g_hi + (size_t)(rowBase + row) * D + ch * 8);
        CP_ASYNC16(sb + so + 32768u, g_lo + (size_t)(rowBase + row) * D + ch * 8);
    }
}
__device__ __forceinline__ void load_A_plain(char* sm, int rowBase, int t) {
    #pragma unroll
    for (int rep = 0; rep < 8; rep++) {
        int idx = rep * 256 + t;
        int row = idx >> 4, ch = idx & 15;
        uint32_t so = (uint32_t)(row * 256) + ((uint32_t)(ch ^ (row & 7)) << 4);
        *(uint4*)(sm + SM_A_HI + so) = *(const uint4*)(g_hi + (size_t)(rowBase + row) * D + ch * 8);
        *(uint4*)(sm + SM_A_LO + so) = *(const uint4*)(g_lo + (size_t)(rowBase + row) * D + ch * 8);
    }
}

// ---------------------------------------------------------------------------
// Kernel 2: triangle sim-GEMM (mma.sync bf16 3-product) + exp row/col sums.
// 130 CTAs x 16 jobs. 256 threads = 2x4 warps, warp tile 64x32.
// ---------------------------------------------------------------------------
__global__ __launch_bounds__(256, 1)
void k_main() {
    extern __shared__ char sm[];
    const uint32_t sb = smem_u32(sm);
    const int t = threadIdx.x, lane = t & 31, wid = t >> 5;
    const int warpM = wid >> 2, warpN = wid & 3;

    // job cursors
    int Ic, Jc; job_ij(blockIdx.x * JOBS_PER_CTA, Ic, Jc);
    int Ip = Ic, Jp = Jc;

    // prologue: B for jobs 0,1
    load_B_async(sb, SM_B(0), Jp * 128, t); CP_COMMIT(); job_adv(Ip, Jp);
    load_B_async(sb, SM_B(1), Jp * 128, t); CP_COMMIT(); job_adv(Ip, Jp);

    // lane-constant ldmatrix address pieces
    const int r7   = lane & 7;
    const int rowA = (lane & 7) + ((lane >> 3) & 1) * 8;  const int c4A = lane >> 4;
    const int rowB = (lane & 7) + ((lane >> 4) << 3);     const int c4B = (lane >> 3) & 1;

    uint32_t aRowHi[4], aRowLo[4];
    #pragma unroll
    for (int mt = 0; mt < 4; mt++) {
        uint32_t ro = (uint32_t)((warpM * 64 + mt * 16 + rowA) * 256);
        aRowHi[mt] = sb + SM_A_HI + ro;
        aRowLo[mt] = sb + SM_A_LO + ro;
    }
    uint32_t bRow[2];
    #pragma unroll
    for (int g = 0; g < 2; g++) bRow[g] = (uint32_t)((warpN * 32 + g * 16 + rowB) * 256);

    float* rowred = (float*)(sm + SM_ROWRED);   // [128][4]
    float* colred = (float*)(sm + SM_COLRED);   // [128][2]
    int Ia = -1;

    for (int jj = 0; jj < JOBS_PER_CTA; jj++) {
        if (Ic != Ia) { load_A_plain(sm, Ic * 128, t); Ia = Ic; }
        CP_WAIT1();
        __syncthreads();

        const uint32_t bHiBase = sb + SM_B(jj & 1);
        const uint32_t bLoBase = bHiBase + 32768u;

        float d[4][4][4];
        #pragma unroll
        for (int mt = 0; mt < 4; mt++)
            #pragma unroll
            for (int nt = 0; nt < 4; nt++)
                #pragma unroll
                for (int q = 0; q < 4; q++) d[mt][nt][q] = 0.0f;

        #pragma unroll
        for (int ks = 0; ks < 8; ks++) {
            uint32_t ah[4][4], al[4][4], bh[8], bl[8];
            const uint32_t offA = (uint32_t)(((2 * ks + c4A) ^ r7) << 4);
            const uint32_t offB = (uint32_t)(((2 * ks + c4B) ^ r7) << 4);
            #pragma unroll
            for (int mt = 0; mt < 4; mt++) {
                ldsm4(ah[mt], aRowHi[mt] + offA);
                ldsm4(al[mt], aRowLo[mt] + offA);
            }
            #pragma unroll
            for (int g = 0; g < 2; g++) {
                ldsm4(bh + g * 4, bHiBase + bRow[g] + offB);
                ldsm4(bl + g * 4, bLoBase + bRow[g] + offB);
            }
            #pragma unroll
            for (int mt = 0; mt < 4; mt++) {
                #pragma unroll
                for (int nt = 0; nt < 4; nt++) {
                    mma_bf16(d[mt][nt], ah[mt], bh[nt * 2], bh[nt * 2 + 1]);
                    mma_bf16(d[mt][nt], ah[mt], bl[nt * 2], bl[nt * 2 + 1]);
                    mma_bf16(d[mt][nt], al[mt], bh[nt * 2], bh[nt * 2 + 1]);
                }
            }
        }
        __syncthreads();   // ldsm reads of this B buffer done
        if (jj + 2 < JOBS_PER_CTA) {
            load_B_async(sb, SM_B(jj & 1), Jp * 128, t); CP_COMMIT(); job_adv(Ip, Jp);
        } else {
            CP_COMMIT();   // empty group keeps wait_group 1 honest at the tail
        }

        // ---- epilogue: exp + row sums + col sums ----
        float rs[8], cc[8];
        #pragma unroll
        for (int u = 0; u < 8; u++) { rs[u] = 0.0f; cc[u] = 0.0f; }
        #pragma unroll
        for (int mt = 0; mt < 4; mt++) {
            #pragma unroll
            for (int nt = 0; nt < 4; nt++) {
                float e0 = ex2f(fmaf(d[mt][nt][0], K2C, -K2C));
                float e1 = ex2f(fmaf(d[mt][nt][1], K2C, -K2C));
                float e2 = ex2f(fmaf(d[mt][nt][2], K2C, -K2C));
                float e3 = ex2f(fmaf(d[mt][nt][3], K2C, -K2C));
                rs[mt * 2 + 0] += e0 + e1;
                rs[mt * 2 + 1] += e2 + e3;
                cc[nt * 2 + 0] += e0 + e2;
                cc[nt * 2 + 1] += e1 + e3;
            }
        }
        // row reduce across lane&3
        #pragma unroll
        for (int u = 0; u < 8; u++) {
            float v = rs[u];
            v += __shfl_xor_sync(0xffffffffu, v, 1);
            v += __shfl_xor_sync(0xffffffffu, v, 2);
            if ((lane & 3) == 0) {
                int r = warpM * 64 + (u >> 1) * 16 + (u & 1) * 8 + (lane >> 2);
                rowred[r * 4 + warpN] = v;
            }
        }
        // col reduce across lane>>2
        #pragma unroll
        for (int u = 0; u < 8; u++) {
            float v = cc[u];
            v += __shfl_xor_sync(0xffffffffu, v, 4);
            v += __shfl_xor_sync(0xffffffffu, v, 8);
            v += __shfl_xor_sync(0xffffffffu, v, 16);
            if (lane < 4) {
                int c = warpN * 32 + (u >> 1) * 8 + (lane & 3) * 2 + (u & 1);
                colred[c * 2 + warpM] = v;
            }
        }
        __syncthreads();
        if (t < 128) {
            float s = rowred[t * 4] + rowred[t * 4 + 1] + rowred[t * 4 + 2] + rowred[t * 4 + 3];
            g_part[(size_t)((Ic << 6) + Jc) * 128 + t] = s;       // row part -> strip I
        } else if (Jc > Ic) {
            int c = t - 128;
            g_part[(size_t)((Jc << 6) + Ic) * 128 + c] = colred[c * 2] + colred[c * 2 + 1];  // col part -> strip J
        }
        __syncthreads();
        job_adv(Ic, Jc);
    }
}

// ---------------------------------------------------------------------------
// Kernel 3: per-row loss terms (parallel, deterministic)
// ---------------------------------------------------------------------------
__global__ void k_rowloss() {
    int r = blockIdx.x * 256 + threadIdx.x;
    int I = r >> 7, rr = r & 127;
    float S = 0.0f;
    const float* base = g_part + (size_t)(I << 6) * 128 + rr;
    #pragma unroll 8
    for (int J = 0; J < NTILE; J++) S += base[(size_t)J * 128];
    float p = g_pos[r];
    float Sf = S + expf(fmaf(10.0f, p, -10.0f));   // prepended positives column
    g_loss[r] = logf(Sf) + 10.0f - 10.0f * p;
}

// ---------------------------------------------------------------------------
// Kernel 4: final sum (single block, deterministic)
// ---------------------------------------------------------------------------
__global__ void k_final(float* __restrict__ out) {
    __shared__ float red[1024];
    float acc = 0.0f;
    for (int r = threadIdx.x; r < TWO_N; r += 1024) acc += g_loss[r];
    red[threadIdx.x] = acc;
    __syncthreads();
    for (int s = 512; s; s >>= 1) {
        if (threadIdx.x < s) red[threadIdx.x] += red[threadIdx.x + s];
        __syncthreads();
    }
    if (threadIdx.x == 0) out[0] = red[0] * (1.0f / (float)TWO_N);
}

// ---------------------------------------------------------------------------
extern "C" void kernel_launch(void* const* d_in, const int* in_sizes, int n_in,
                              void* d_out, int out_size) {
    const float* zi = (const float*)d_in[0];
    const float* zj = (const float*)d_in[1];
    float* out = (float*)d_out;

    cudaFuncSetAttribute(k_main, cudaFuncAttributeMaxDynamicSharedMemorySize, SMEM_BYTES);

    k_prep<<<NROWS / 8, 256>>>(zi, zj);
    k_main<<<GRID_MAIN, 256, SMEM_BYTES>>>();
    k_rowloss<<<TWO_N / 256, 256>>>();
    k_final<<<1, 1024>>>(out);
}

// round 5
// speedup vs baseline: 6.6461x; 1.0764x over previous
#include <cuda_runtime.h>
#include <cuda_bf16.h>
#include <math.h>
#include <stdint.h>

#define NROWS 4096
#define TWO_N 8192
#define D 128
#define NTILE 64
#define NJOBS 2080                  // 64*65/2 triangle tiles
#define GRID_MAIN 148
#define K2C 14.4269504088896340f    // 10 / ln(2)
#define PSC 3.798282565009841f      // sqrt(10/ln(2)) pre-scale

// ---------------- device scratch (allocation-free) ----------------
__device__ __nv_bfloat16  g_hi[TWO_N * D];     // sqrt(K2C)-scaled normalized reps (hi)
__device__ __nv_bfloat16  g_lo[TWO_N * D];     // residual (lo)
__device__ float          g_pos[TWO_N];
__device__ float          g_part[NTILE * NTILE * 128];
__device__ float          g_bsum[32];
__device__ unsigned int   g_cnt;               // zero-init; self-resetting

// ---------------- smem map (dynamic) ----------------
#define SM_A_HI   0
#define SM_A_LO   32768
#define SM_B(s)   (65536 + (s) * 65536)
#define SM_ROWRED 196608
#define SM_COLRED 198656
#define SMEM_BYTES 199680

// ---------------- helpers ----------------
__device__ __forceinline__ uint32_t smem_u32(const void* p) {
    uint32_t a;
    asm("{ .reg .u64 t; cvta.to.shared.u64 t, %1; cvt.u32.u64 %0, t; }" : "=r"(a) : "l"(p));
    return a;
}
__device__ __forceinline__ float ex2f(float x) {
    float r; asm("ex2.approx.ftz.f32 %0, %1;" : "=f"(r) : "f"(x)); return r;
}
__device__ __forceinline__ void ldsm4(uint32_t* r, uint32_t addr) {
    asm volatile("ldmatrix.sync.aligned.m8n8.x4.shared.b16 {%0,%1,%2,%3}, [%4];"
                 : "=r"(r[0]), "=r"(r[1]), "=r"(r[2]), "=r"(r[3]) : "r"(addr));
}
__device__ __forceinline__ void mma_bf16(float* d, const uint32_t* a, uint32_t b0, uint32_t b1) {
    asm volatile("mma.sync.aligned.m16n8k16.row.col.f32.bf16.bf16.f32 "
                 "{%0,%1,%2,%3}, {%4,%5,%6,%7}, {%8,%9}, {%0,%1,%2,%3};"
                 : "+f"(d[0]), "+f"(d[1]), "+f"(d[2]), "+f"(d[3])
                 : "r"(a[0]), "r"(a[1]), "r"(a[2]), "r"(a[3]), "r"(b0), "r"(b1));
}
#define CP_ASYNC16(sa, ga) \
    asm volatile("cp.async.cg.shared.global [%0], [%1], 16;" :: "r"(sa), "l"(ga))
#define CP_COMMIT() asm volatile("cp.async.commit_group;" ::: "memory")
#define CP_WAIT1()  asm volatile("cp.async.wait_group 1;" ::: "memory")

__device__ __forceinline__ void job_ij(int g, int& I, int& J) {
    int i = 0, off = 0;
    while (off + (NTILE - i) <= g) { off += NTILE - i; i++; }
    I = i; J = i + (g - off);
}
__device__ __forceinline__ void job_adv(int& I, int& J) {
    if (++J == NTILE) { ++I; J = I; }
}

// ---------------------------------------------------------------------------
// Kernel 1: normalize pair rows (r, r+N), sqrt(K2C) pre-scale, bf16 hi/lo
// split, positive sims. One warp per pair.
// ---------------------------------------------------------------------------
__global__ void k_prep(const float* __restrict__ zi, const float* __restrict__ zj) {
    int warp = threadIdx.x >> 5, lane = threadIdx.x & 31;
    int p = blockIdx.x * 8 + warp;
    float4 a = ((const float4*)(zi + (size_t)p * D))[lane];
    float4 b = ((const float4*)(zj + (size_t)p * D))[lane];
    float sa = a.x*a.x + a.y*a.y + a.z*a.z + a.w*a.w;
    float sb = b.x*b.x + b.y*b.y + b.z*b.z + b.w*b.w;
    float dp = a.x*b.x + a.y*b.y + a.z*b.z + a.w*b.w;
    #pragma unroll
    for (int o = 16; o; o >>= 1) {
        sa += __shfl_xor_sync(0xffffffffu, sa, o);
        sb += __shfl_xor_sync(0xffffffffu, sb, o);
        dp += __shfl_xor_sync(0xffffffffu, dp, o);
    }
    float ia = 1.0f / fmaxf(sqrtf(sa), 1e-8f);
    float ib = 1.0f / fmaxf(sqrtf(sb), 1e-8f);
    if (lane == 0) {
        float pos = dp * ia * ib;
        g_pos[p] = pos;
        g_pos[p + NROWS] = pos;
    }
    float fa = ia * PSC, fb = ib * PSC;
    float wa[4] = {a.x*fa, a.y*fa, a.z*fa, a.w*fa};
    float wb[4] = {b.x*fb, b.y*fb, b.z*fb, b.w*fb};
    __nv_bfloat16 ha[4], la[4], hb[4], lb[4];
    #pragma unroll
    for (int q = 0; q < 4; q++) {
        ha[q] = __float2bfloat16(wa[q]); la[q] = __float2bfloat16(wa[q] - __bfloat162float(ha[q]));
        hb[q] = __float2bfloat16(wb[q]); lb[q] = __float2bfloat16(wb[q] - __bfloat162float(hb[q]));
    }
    *(uint2*)(g_hi + (size_t)p * D + lane * 4) = *(uint2*)ha;
    *(uint2*)(g_lo + (size_t)p * D + lane * 4) = *(uint2*)la;
    *(uint2*)(g_hi + (size_t)(p + NROWS) * D + lane * 4) = *(uint2*)hb;
    *(uint2*)(g_lo + (size_t)(p + NROWS) * D + lane * 4) = *(uint2*)lb;
}

// ---------------------------------------------------------------------------
// tile loaders (XOR-swizzled 16B chunks, 256B rows)
// ---------------------------------------------------------------------------
__device__ __forceinline__ void load_B_async(uint32_t sb, uint32_t off, int rowBase, int t) {
    #pragma unroll
    for (int rep = 0; rep < 8; rep++) {
        int idx = rep * 256 + t;
        int row = idx >> 4, ch = idx & 15;
        uint32_t so = off + (uint32_t)(row * 256) + ((uint32_t)(ch ^ (row & 7)) << 4);
        CP_ASYNC16(sb + so,          g_hi + (size_t)(rowBase + row) * D + ch * 8);
        CP_ASYNC16(sb + so + 32768u, g_lo + (size_t)(rowBase + row) * D + ch * 8);
    }
}
__device__ __forceinline__ void load_A_plain(char* sm, int rowBase, int t) {
    #pragma unroll
    for (int rep = 0; rep < 8; rep++) {
        int idx = rep * 256 + t;
        int row = idx >> 4, ch = idx & 15;
        uint32_t so = (uint32_t)(row * 256) + ((uint32_t)(ch ^ (row & 7)) << 4);
        *(uint4*)(sm + SM_A_HI + so) = *(const uint4*)(g_hi + (size_t)(rowBase + row) * D + ch * 8);
        *(uint4*)(sm + SM_A_LO + so) = *(const uint4*)(g_lo + (size_t)(rowBase + row) * D + ch * 8);
    }
}

// ---------------------------------------------------------------------------
// Kernel 2: triangle sim-GEMM + exp row/col sums. 148 CTAs, even job split.
// ---------------------------------------------------------------------------
__global__ __launch_bounds__(256, 1)
void k_main() {
    extern __shared__ char sm[];
    const uint32_t sb = smem_u32(sm);
    const int t = threadIdx.x, lane = t & 31, wid = t >> 5;
    const int warpM = wid >> 2, warpN = wid & 3;

    const int jb = (int)(((long)blockIdx.x * NJOBS) / GRID_MAIN);
    const int je = (int)(((long)(blockIdx.x + 1) * NJOBS) / GRID_MAIN);
    const int njobs = je - jb;

    int Ic, Jc; job_ij(jb, Ic, Jc);
    int Ip = Ic, Jp = Jc;

    load_B_async(sb, SM_B(0), Jp * 128, t); CP_COMMIT(); job_adv(Ip, Jp);
    load_B_async(sb, SM_B(1), Jp * 128, t); CP_COMMIT(); job_adv(Ip, Jp);

    const int r7   = lane & 7;
    const int rowA = (lane & 7) + ((lane >> 3) & 1) * 8;  const int c4A = lane >> 4;
    const int rowB = (lane & 7) + ((lane >> 4) << 3);     const int c4B = (lane >> 3) & 1;

    uint32_t aRowHi[4], aRowLo[4];
    #pragma unroll
    for (int mt = 0; mt < 4; mt++) {
        uint32_t ro = (uint32_t)((warpM * 64 + mt * 16 + rowA) * 256);
        aRowHi[mt] = sb + SM_A_HI + ro;
        aRowLo[mt] = sb + SM_A_LO + ro;
    }
    uint32_t bRow[2];
    #pragma unroll
    for (int g = 0; g < 2; g++) bRow[g] = (uint32_t)((warpN * 32 + g * 16 + rowB) * 256);

    float* rowred = (float*)(sm + SM_ROWRED);
    float* colred = (float*)(sm + SM_COLRED);
    int Ia = -1;

    for (int jj = 0; jj < njobs; jj++) {
        if (Ic != Ia) { load_A_plain(sm, Ic * 128, t); Ia = Ic; }
        CP_WAIT1();
        __syncthreads();

        const uint32_t bHiBase = sb + SM_B(jj & 1);
        const uint32_t bLoBase = bHiBase + 32768u;

        float d[4][4][4];
        #pragma unroll
        for (int mt = 0; mt < 4; mt++)
            #pragma unroll
            for (int nt = 0; nt < 4; nt++)
                #pragma unroll
                for (int q = 0; q < 4; q++) d[mt][nt][q] = -K2C;  // folds the -10 shift

        #pragma unroll
        for (int ks = 0; ks < 8; ks++) {
            uint32_t ah[4][4], al[4][4], bh[8], bl[8];
            const uint32_t offA = (uint32_t)(((2 * ks + c4A) ^ r7) << 4);
            const uint32_t offB = (uint32_t)(((2 * ks + c4B) ^ r7) << 4);
            #pragma unroll
            for (int mt = 0; mt < 4; mt++) {
                ldsm4(ah[mt], aRowHi[mt] + offA);
                ldsm4(al[mt], aRowLo[mt] + offA);
            }
            #pragma unroll
            for (int g = 0; g < 2; g++) {
                ldsm4(bh + g * 4, bHiBase + bRow[g] + offB);
                ldsm4(bl + g * 4, bLoBase + bRow[g] + offB);
            }
            #pragma unroll
            for (int mt = 0; mt < 4; mt++) {
                #pragma unroll
                for (int nt = 0; nt < 4; nt++) {
                    mma_bf16(d[mt][nt], ah[mt], bh[nt * 2], bh[nt * 2 + 1]);
                    mma_bf16(d[mt][nt], ah[mt], bl[nt * 2], bl[nt * 2 + 1]);
                    mma_bf16(d[mt][nt], al[mt], bh[nt * 2], bh[nt * 2 + 1]);
                }
            }
        }
        __syncthreads();
        if (jj + 2 < njobs) {
            load_B_async(sb, SM_B(jj & 1), Jp * 128, t); CP_COMMIT(); job_adv(Ip, Jp);
        } else {
            CP_COMMIT();
        }

        // ---- epilogue: exp + row sums + col sums (d already = 10*sim/ln2 - 10/ln2) ----
        float rs[8], cc[8];
        #pragma unroll
        for (int u = 0; u < 8; u++) { rs[u] = 0.0f; cc[u] = 0.0f; }
        #pragma unroll
        for (int mt = 0; mt < 4; mt++) {
            #pragma unroll
            for (int nt = 0; nt < 4; nt++) {
                float e0 = ex2f(d[mt][nt][0]);
                float e1 = ex2f(d[mt][nt][1]);
                float e2 = ex2f(d[mt][nt][2]);
                float e3 = ex2f(d[mt][nt][3]);
                rs[mt * 2 + 0] += e0 + e1;
                rs[mt * 2 + 1] += e2 + e3;
                cc[nt * 2 + 0] += e0 + e2;
                cc[nt * 2 + 1] += e1 + e3;
            }
        }
        #pragma unroll
        for (int u = 0; u < 8; u++) {
            float v = rs[u];
            v += __shfl_xor_sync(0xffffffffu, v, 1);
            v += __shfl_xor_sync(0xffffffffu, v, 2);
            if ((lane & 3) == 0) {
                int r = warpM * 64 + (u >> 1) * 16 + (u & 1) * 8 + (lane >> 2);
                rowred[r * 4 + warpN] = v;
            }
        }
        #pragma unroll
        for (int u = 0; u < 8; u++) {
            float v = cc[u];
            v += __shfl_xor_sync(0xffffffffu, v, 4);
            v += __shfl_xor_sync(0xffffffffu, v, 8);
            v += __shfl_xor_sync(0xffffffffu, v, 16);
            if (lane < 4) {
                int c = warpN * 32 + (u >> 1) * 8 + (lane & 3) * 2 + (u & 1);
                colred[c * 2 + warpM] = v;
            }
        }
        __syncthreads();
        if (t < 128) {
            float s = rowred[t * 4] + rowred[t * 4 + 1] + rowred[t * 4 + 2] + rowred[t * 4 + 3];
            g_part[(size_t)((Ic << 6) + Jc) * 128 + t] = s;
        } else if (Jc > Ic) {
            int c = t - 128;
            g_part[(size_t)((Jc << 6) + Ic) * 128 + c] = colred[c * 2] + colred[c * 2 + 1];
        }
        __syncthreads();
        job_adv(Ic, Jc);
    }
}

// ---------------------------------------------------------------------------
// Kernel 3: per-row loss + full reduction (last-block-done pattern).
// grid = 32 x 256 threads, 1 row per thread. Deterministic arithmetic order.
// ---------------------------------------------------------------------------
__global__ void k_tail(float* __restrict__ out) {
    __shared__ float red[256];
    __shared__ bool isLast;
    int r = blockIdx.x * 256 + threadIdx.x;
    int I = r >> 7, rr = r & 127;
    float S = 0.0f;
    const float* base = g_part + (size_t)(I << 6) * 128 + rr;
    #pragma unroll 8
    for (int J = 0; J < NTILE; J++) S += base[(size_t)J * 128];
    float p = g_pos[r];
    float Sf = S + expf(fmaf(10.0f, p, -10.0f));
    red[threadIdx.x] = logf(Sf) + 10.0f - 10.0f * p;
    __syncthreads();
    for (int s = 128; s; s >>= 1) {
        if (threadIdx.x < s) red[threadIdx.x] += red[threadIdx.x + s];
        __syncthreads();
    }
    if (threadIdx.x == 0) {
        g_bsum[blockIdx.x] = red[0];
        __threadfence();
        unsigned int done = atomicAdd(&g_cnt, 1u);
        isLast = (done == 31u);
    }
    __syncthreads();
    if (isLast && threadIdx.x == 0) {
        float acc = 0.0f;
        #pragma unroll
        for (int b = 0; b < 32; b++) acc += ((volatile float*)g_bsum)[b];
        out[0] = acc * (1.0f / (float)TWO_N);
        g_cnt = 0;   // self-reset for next graph replay
    }
}

// ---------------------------------------------------------------------------
extern "C" void kernel_launch(void* const* d_in, const int* in_sizes, int n_in,
                              void* d_out, int out_size) {
    const float* zi = (const float*)d_in[0];
    const float* zj = (const float*)d_in[1];
    float* out = (float*)d_out;

    cudaFuncSetAttribute(k_main, cudaFuncAttributeMaxDynamicSharedMemorySize, SMEM_BYTES);

    k_prep<<<NROWS / 8, 256>>>(zi, zj);
    k_main<<<GRID_MAIN, 256, SMEM_BYTES>>>();
    k_tail<<<32, 256>>>(out);
}

// round 6
// speedup vs baseline: 11.7158x; 1.7628x over previous
#include <cuda_runtime.h>
#include <cuda_fp16.h>
#include <math.h>
#include <stdint.h>

#define NROWS 4096
#define TWO_N 8192
#define D 128
#define NTILE 64
#define NJOBS 2080                  // 64*65/2 triangle tiles
#define GRID_MAIN 148
#define K2C 14.4269504088896340f    // 10 / ln(2)
#define PSC 3.798282565009841f      // sqrt(10/ln(2)) pre-scale

// ---------------- device scratch (allocation-free) ----------------
__device__ __half         g_h[TWO_N * D];      // sqrt(K2C)-scaled normalized reps, fp16
__device__ float          g_pos[TWO_N];
__device__ float          g_part[NTILE * NTILE * 128];
__device__ float          g_bsum[32];
__device__ unsigned int   g_cnt;               // zero-init; self-resetting

// ---------------- smem map (dynamic) ----------------
#define SM_A      0
#define SM_B(s)   (32768 + (s) * 32768)
#define SM_ROWRED 98304
#define SM_COLRED 100352
#define SMEM_BYTES 101376

// ---------------- helpers ----------------
__device__ __forceinline__ uint32_t smem_u32(const void* p) {
    uint32_t a;
    asm("{ .reg .u64 t; cvta.to.shared.u64 t, %1; cvt.u32.u64 %0, t; }" : "=r"(a) : "l"(p));
    return a;
}
__device__ __forceinline__ float ex2f(float x) {
    float r; asm("ex2.approx.ftz.f32 %0, %1;" : "=f"(r) : "f"(x)); return r;
}
__device__ __forceinline__ void ldsm4(uint32_t* r, uint32_t addr) {
    asm volatile("ldmatrix.sync.aligned.m8n8.x4.shared.b16 {%0,%1,%2,%3}, [%4];"
                 : "=r"(r[0]), "=r"(r[1]), "=r"(r[2]), "=r"(r[3]) : "r"(addr));
}
__device__ __forceinline__ void mma_fp16(float* d, const uint32_t* a, uint32_t b0, uint32_t b1) {
    asm volatile("mma.sync.aligned.m16n8k16.row.col.f32.f16.f16.f32 "
                 "{%0,%1,%2,%3}, {%4,%5,%6,%7}, {%8,%9}, {%0,%1,%2,%3};"
                 : "+f"(d[0]), "+f"(d[1]), "+f"(d[2]), "+f"(d[3])
                 : "r"(a[0]), "r"(a[1]), "r"(a[2]), "r"(a[3]), "r"(b0), "r"(b1));
}
#define CP_ASYNC16(sa, ga) \
    asm volatile("cp.async.cg.shared.global [%0], [%1], 16;" :: "r"(sa), "l"(ga))
#define CP_COMMIT() asm volatile("cp.async.commit_group;" ::: "memory")
#define CP_WAIT1()  asm volatile("cp.async.wait_group 1;" ::: "memory")

__device__ __forceinline__ void job_ij(int g, int& I, int& J) {
    int i = 0, off = 0;
    while (off + (NTILE - i) <= g) { off += NTILE - i; i++; }
    I = i; J = i + (g - off);
}
__device__ __forceinline__ void job_adv(int& I, int& J) {
    if (++J == NTILE) { ++I; J = I; }
}

// ---------------------------------------------------------------------------
// Kernel 1: normalize pair rows (r, r+N), sqrt(K2C) pre-scale, fp16 cast,
// positive sims. One warp per pair.
// ---------------------------------------------------------------------------
__global__ void k_prep(const float* __restrict__ zi, const float* __restrict__ zj) {
    int warp = threadIdx.x >> 5, lane = threadIdx.x & 31;
    int p = blockIdx.x * 8 + warp;
    float4 a = ((const float4*)(zi + (size_t)p * D))[lane];
    float4 b = ((const float4*)(zj + (size_t)p * D))[lane];
    float sa = a.x*a.x + a.y*a.y + a.z*a.z + a.w*a.w;
    float sb = b.x*b.x + b.y*b.y + b.z*b.z + b.w*b.w;
    float dp = a.x*b.x + a.y*b.y + a.z*b.z + a.w*b.w;
    #pragma unroll
    for (int o = 16; o; o >>= 1) {
        sa += __shfl_xor_sync(0xffffffffu, sa, o);
        sb += __shfl_xor_sync(0xffffffffu, sb, o);
        dp += __shfl_xor_sync(0xffffffffu, dp, o);
    }
    float ia = 1.0f / fmaxf(sqrtf(sa), 1e-8f);
    float ib = 1.0f / fmaxf(sqrtf(sb), 1e-8f);
    if (lane == 0) {
        float pos = dp * ia * ib;
        g_pos[p] = pos;
        g_pos[p + NROWS] = pos;
    }
    float fa = ia * PSC, fb = ib * PSC;
    __half ha[4], hb[4];
    ha[0] = __float2half(a.x*fa); ha[1] = __float2half(a.y*fa);
    ha[2] = __float2half(a.z*fa); ha[3] = __float2half(a.w*fa);
    hb[0] = __float2half(b.x*fb); hb[1] = __float2half(b.y*fb);
    hb[2] = __float2half(b.z*fb); hb[3] = __float2half(b.w*fb);
    *(uint2*)(g_h + (size_t)p * D + lane * 4)           = *(uint2*)ha;
    *(uint2*)(g_h + (size_t)(p + NROWS) * D + lane * 4) = *(uint2*)hb;
}

// ---------------------------------------------------------------------------
// tile loaders (XOR-swizzled 16B chunks, 256B rows of 128 fp16)
// ---------------------------------------------------------------------------
__device__ __forceinline__ void load_B_async(uint32_t sb, uint32_t off, int rowBase, int t) {
    #pragma unroll
    for (int rep = 0; rep < 8; rep++) {
        int idx = rep * 256 + t;
        int row = idx >> 4, ch = idx & 15;
        uint32_t so = off + (uint32_t)(row * 256) + ((uint32_t)(ch ^ (row & 7)) << 4);
        CP_ASYNC16(sb + so, g_h + (size_t)(rowBase + row) * D + ch * 8);
    }
}
__device__ __forceinline__ void load_A_plain(char* sm, int rowBase, int t) {
    #pragma unroll
    for (int rep = 0; rep < 8; rep++) {
        int idx = rep * 256 + t;
        int row = idx >> 4, ch = idx & 15;
        uint32_t so = (uint32_t)(row * 256) + ((uint32_t)(ch ^ (row & 7)) << 4);
        *(uint4*)(sm + SM_A + so) = *(const uint4*)(g_h + (size_t)(rowBase + row) * D + ch * 8);
    }
}

// ---------------------------------------------------------------------------
// Kernel 2: triangle sim-GEMM (fp16 single-product) + exp row/col sums.
// 148 CTAs, even job split; 256 threads = 2x4 warps, warp tile 64x32.
// ---------------------------------------------------------------------------
__global__ __launch_bounds__(256, 1)
void k_main() {
    extern __shared__ char sm[];
    const uint32_t sb = smem_u32(sm);
    const int t = threadIdx.x, lane = t & 31, wid = t >> 5;
    const int warpM = wid >> 2, warpN = wid & 3;

    const int jb = (int)(((long)blockIdx.x * NJOBS) / GRID_MAIN);
    const int je = (int)(((long)(blockIdx.x + 1) * NJOBS) / GRID_MAIN);
    const int njobs = je - jb;

    int Ic, Jc; job_ij(jb, Ic, Jc);
    int Ip = Ic, Jp = Jc;

    load_B_async(sb, SM_B(0), Jp * 128, t); CP_COMMIT(); job_adv(Ip, Jp);
    load_B_async(sb, SM_B(1), Jp * 128, t); CP_COMMIT(); job_adv(Ip, Jp);

    const int r7   = lane & 7;
    const int rowA = (lane & 7) + ((lane >> 3) & 1) * 8;  const int c4A = lane >> 4;
    const int rowB = (lane & 7) + ((lane >> 4) << 3);     const int c4B = (lane >> 3) & 1;

    uint32_t aRow[4];
    #pragma unroll
    for (int mt = 0; mt < 4; mt++)
        aRow[mt] = sb + SM_A + (uint32_t)((warpM * 64 + mt * 16 + rowA) * 256);
    uint32_t bRow[2];
    #pragma unroll
    for (int g = 0; g < 2; g++) bRow[g] = (uint32_t)((warpN * 32 + g * 16 + rowB) * 256);

    float* rowred = (float*)(sm + SM_ROWRED);
    float* colred = (float*)(sm + SM_COLRED);
    int Ia = -1;

    for (int jj = 0; jj < njobs; jj++) {
        if (Ic != Ia) { load_A_plain(sm, Ic * 128, t); Ia = Ic; }
        CP_WAIT1();
        __syncthreads();

        const uint32_t bBase = sb + SM_B(jj & 1);

        float d[4][4][4];
        #pragma unroll
        for (int mt = 0; mt < 4; mt++)
            #pragma unroll
            for (int nt = 0; nt < 4; nt++)
                #pragma unroll
                for (int q = 0; q < 4; q++) d[mt][nt][q] = -K2C;  // folds the -10 shift

        #pragma unroll
        for (int ks = 0; ks < 8; ks++) {
            uint32_t ah[4][4], bh[8];
            const uint32_t offA = (uint32_t)(((2 * ks + c4A) ^ r7) << 4);
            const uint32_t offB = (uint32_t)(((2 * ks + c4B) ^ r7) << 4);
            #pragma unroll
            for (int mt = 0; mt < 4; mt++) ldsm4(ah[mt], aRow[mt] + offA);
            #pragma unroll
            for (int g = 0; g < 2; g++) ldsm4(bh + g * 4, bBase + bRow[g] + offB);
            #pragma unroll
            for (int mt = 0; mt < 4; mt++)
                #pragma unroll
                for (int nt = 0; nt < 4; nt++)
                    mma_fp16(d[mt][nt], ah[mt], bh[nt * 2], bh[nt * 2 + 1]);
        }
        __syncthreads();
        if (jj + 2 < njobs) {
            load_B_async(sb, SM_B(jj & 1), Jp * 128, t); CP_COMMIT(); job_adv(Ip, Jp);
        } else {
            CP_COMMIT();
        }

        // ---- epilogue: exp + row sums + col sums (d = 10*sim/ln2 - 10/ln2) ----
        float rs[8], cc[8];
        #pragma unroll
        for (int u = 0; u < 8; u++) { rs[u] = 0.0f; cc[u] = 0.0f; }
        #pragma unroll
        for (int mt = 0; mt < 4; mt++) {
            #pragma unroll
            for (int nt = 0; nt < 4; nt++) {
                float e0 = ex2f(d[mt][nt][0]);
                float e1 = ex2f(d[mt][nt][1]);
                float e2 = ex2f(d[mt][nt][2]);
                float e3 = ex2f(d[mt][nt][3]);
                rs[mt * 2 + 0] += e0 + e1;
                rs[mt * 2 + 1] += e2 + e3;
                cc[nt * 2 + 0] += e0 + e2;
                cc[nt * 2 + 1] += e1 + e3;
            }
        }
        #pragma unroll
        for (int u = 0; u < 8; u++) {
            float v = rs[u];
            v += __shfl_xor_sync(0xffffffffu, v, 1);
            v += __shfl_xor_sync(0xffffffffu, v, 2);
            if ((lane & 3) == 0) {
                int r = warpM * 64 + (u >> 1) * 16 + (u & 1) * 8 + (lane >> 2);
                rowred[r * 4 + warpN] = v;
            }
        }
        #pragma unroll
        for (int u = 0; u < 8; u++) {
            float v = cc[u];
            v += __shfl_xor_sync(0xffffffffu, v, 4);
            v += __shfl_xor_sync(0xffffffffu, v, 8);
            v += __shfl_xor_sync(0xffffffffu, v, 16);
            if (lane < 4) {
                int c = warpN * 32 + (u >> 1) * 8 + (lane & 3) * 2 + (u & 1);
                colred[c * 2 + warpM] = v;
            }
        }
        __syncthreads();
        if (t < 128) {
            float s = rowred[t * 4] + rowred[t * 4 + 1] + rowred[t * 4 + 2] + rowred[t * 4 + 3];
            g_part[(size_t)((Ic << 6) + Jc) * 128 + t] = s;
        } else if (Jc > Ic) {
            int c = t - 128;
            g_part[(size_t)((Jc << 6) + Ic) * 128 + c] = colred[c * 2] + colred[c * 2 + 1];
        }
        __syncthreads();
        job_adv(Ic, Jc);
    }
}

// ---------------------------------------------------------------------------
// Kernel 3: per-row loss + full reduction (last-block-done pattern).
// ---------------------------------------------------------------------------
__global__ void k_tail(float* __restrict__ out) {
    __shared__ float red[256];
    __shared__ bool isLast;
    int r = blockIdx.x * 256 + threadIdx.x;
    int I = r >> 7, rr = r & 127;
    float S = 0.0f;
    const float* base = g_part + (size_t)(I << 6) * 128 + rr;
    #pragma unroll 8
    for (int J = 0; J < NTILE; J++) S += base[(size_t)J * 128];
    float p = g_pos[r];
    float Sf = S + expf(fmaf(10.0f, p, -10.0f));
    red[threadIdx.x] = logf(Sf) + 10.0f - 10.0f * p;
    __syncthreads();
    for (int s = 128; s; s >>= 1) {
        if (threadIdx.x < s) red[threadIdx.x] += red[threadIdx.x + s];
        __syncthreads();
    }
    if (threadIdx.x == 0) {
        g_bsum[blockIdx.x] = red[0];
        __threadfence();
        unsigned int done = atomicAdd(&g_cnt, 1u);
        isLast = (done == 31u);
    }
    __syncthreads();
    if (isLast && threadIdx.x == 0) {
        float acc = 0.0f;
        #pragma unroll
        for (int b = 0; b < 32; b++) acc += ((volatile float*)g_bsum)[b];
        out[0] = acc * (1.0f / (float)TWO_N);
        g_cnt = 0;   // self-reset for next graph replay
    }
}

// ---------------------------------------------------------------------------
extern "C" void kernel_launch(void* const* d_in, const int* in_sizes, int n_in,
                              void* d_out, int out_size) {
    const float* zi = (const float*)d_in[0];
    const float* zj = (const float*)d_in[1];
    float* out = (float*)d_out;

    cudaFuncSetAttribute(k_main, cudaFuncAttributeMaxDynamicSharedMemorySize, SMEM_BYTES);

    k_prep<<<NROWS / 8, 256>>>(zi, zj);
    k_main<<<GRID_MAIN, 256, SMEM_BYTES>>>();
    k_tail<<<32, 256>>>(out);
}